// round 1
// baseline (speedup 1.0000x reference)
#include <cuda_runtime.h>
#include <math.h>
#include <float.h>

// Problem constants
#define BS_TOK 2048          // B*S
#define NQn 16               // query slots
#define NSn 8                // key/value slots
#define KDn 64
#define NKn 2048
#define VDn 128
#define MEMn 512
#define LN_EPS 1e-5f

// Scratch (static device globals; no runtime allocation allowed)
__device__ float g_q[BS_TOK * NQn * KDn];        // post-LN queries   (32768 x 64)   8 MB
__device__ float g_knorm[NSn * NKn * KDn];       // normalized keys   (8 x 2048 x 64) 4 MB
__device__ float g_att[BS_TOK * NQn * VDn];      // attn + residual   (32768 x 128) 16 MB

// ---------------------------------------------------------------------------
// Generic 64x64x16 tiled fp32 GEMM body: C = A(MxK) @ B(KxN) + bias
// 256 threads, 4x4 register microtile. M,N divisible by 64; K divisible by 16.
// REMAP: scatter rows for the final split-output layout.
// ---------------------------------------------------------------------------
template<bool REMAP>
__device__ __forceinline__ void gemm_body(const float* __restrict__ A,
                                          const float* __restrict__ B,
                                          const float* __restrict__ bias,
                                          float* __restrict__ C,
                                          int M, int N, int K)
{
    __shared__ float As[16][65];   // [k][m], padded
    __shared__ float Bs[16][64];   // [k][n]

    const int tid  = threadIdx.x;        // 0..255
    const int tx   = tid & 15;
    const int ty   = tid >> 4;
    const int m0   = blockIdx.y << 6;
    const int n0   = blockIdx.x << 6;
    const int arow = tid >> 2;           // 0..63
    const int akq  = tid & 3;            // 0..3 (float4 within 16-wide k tile)
    const int bk   = tid >> 4;           // 0..15
    const int bnq  = tid & 15;           // 0..15

    float acc[4][4];
#pragma unroll
    for (int i = 0; i < 4; ++i)
#pragma unroll
        for (int j = 0; j < 4; ++j) acc[i][j] = 0.f;

    for (int k0 = 0; k0 < K; k0 += 16) {
        float4 av = *(const float4*)(A + (size_t)(m0 + arow) * K + k0 + (akq << 2));
        As[(akq << 2) + 0][arow] = av.x;
        As[(akq << 2) + 1][arow] = av.y;
        As[(akq << 2) + 2][arow] = av.z;
        As[(akq << 2) + 3][arow] = av.w;
        *(float4*)(&Bs[bk][bnq << 2]) =
            *(const float4*)(B + (size_t)(k0 + bk) * N + n0 + (bnq << 2));
        __syncthreads();

#pragma unroll
        for (int k = 0; k < 16; ++k) {
            float a0 = As[k][(ty << 2) + 0];
            float a1 = As[k][(ty << 2) + 1];
            float a2 = As[k][(ty << 2) + 2];
            float a3 = As[k][(ty << 2) + 3];
            float b0 = Bs[k][(tx << 2) + 0];
            float b1 = Bs[k][(tx << 2) + 1];
            float b2 = Bs[k][(tx << 2) + 2];
            float b3 = Bs[k][(tx << 2) + 3];
            acc[0][0] += a0 * b0; acc[0][1] += a0 * b1; acc[0][2] += a0 * b2; acc[0][3] += a0 * b3;
            acc[1][0] += a1 * b0; acc[1][1] += a1 * b1; acc[1][2] += a1 * b2; acc[1][3] += a1 * b3;
            acc[2][0] += a2 * b0; acc[2][1] += a2 * b1; acc[2][2] += a2 * b2; acc[2][3] += a2 * b3;
            acc[3][0] += a3 * b0; acc[3][1] += a3 * b1; acc[3][2] += a3 * b2; acc[3][3] += a3 * b3;
        }
        __syncthreads();
    }

#pragma unroll
    for (int i = 0; i < 4; ++i) {
        const int r = m0 + (ty << 2) + i;
#pragma unroll
        for (int j = 0; j < 4; ++j) {
            const int n = n0 + (tx << 2) + j;
            const float v = acc[i][j] + bias[n];
            if (REMAP) {
                // r = token*16 + slot ; output = [half0: slots 0..7][half1: slots 8..15]
                const int token = r >> 4;
                const int slot  = r & 15;
                const size_t base = (slot < NSn) ? 0 : (size_t)BS_TOK * NSn * MEMn;
                C[base + (size_t)(token * NSn + (slot & 7)) * MEMn + n] = v;
            } else {
                C[(size_t)r * N + n] = v;
            }
        }
    }
}

__global__ void gemm_q_kernel(const float* __restrict__ x,
                              const float* __restrict__ Wq,
                              const float* __restrict__ bq)
{
    gemm_body<false>(x, Wq, bq, g_q, BS_TOK, NQn * KDn, 512);
}

__global__ void gemm_res_kernel(const float* __restrict__ Wres,
                                const float* __restrict__ bres)
{
    gemm_body<false>(g_q, Wres, bres, g_att, BS_TOK * NQn, VDn, KDn);
}

__global__ void gemm_out_kernel(const float* __restrict__ Wmem,
                                const float* __restrict__ bmem,
                                float* __restrict__ out)
{
    gemm_body<true>(g_att, Wmem, bmem, out, BS_TOK * NQn, MEMn, VDn);
}

// ---------------------------------------------------------------------------
// In-place LayerNorm over rows of 64 (two-pass, matches mean((q-mu)^2))
// One warp per row.
// ---------------------------------------------------------------------------
__global__ void ln_kernel(const float* __restrict__ gamma,
                          const float* __restrict__ beta)
{
    const int warp = (blockIdx.x * blockDim.x + threadIdx.x) >> 5;
    const int lane = threadIdx.x & 31;
    if (warp >= BS_TOK * NQn) return;
    float* row = g_q + (size_t)warp * KDn;
    float v0 = row[lane], v1 = row[lane + 32];
    float s = v0 + v1;
#pragma unroll
    for (int o = 16; o > 0; o >>= 1) s += __shfl_xor_sync(0xffffffffu, s, o);
    const float mu = s * (1.f / 64.f);
    const float d0 = v0 - mu, d1 = v1 - mu;
    float sq = d0 * d0 + d1 * d1;
#pragma unroll
    for (int o = 16; o > 0; o >>= 1) sq += __shfl_xor_sync(0xffffffffu, sq, o);
    const float inv = rsqrtf(sq * (1.f / 64.f) + LN_EPS);
    row[lane]      = d0 * inv * gamma[lane]      + beta[lane];
    row[lane + 32] = d1 * inv * gamma[lane + 32] + beta[lane + 32];
}

// ---------------------------------------------------------------------------
// L2-normalize key rows: g_knorm = keys / ||keys||. One warp per row.
// ---------------------------------------------------------------------------
__global__ void knorm_kernel(const float* __restrict__ keys)
{
    const int warp = (blockIdx.x * blockDim.x + threadIdx.x) >> 5;
    const int lane = threadIdx.x & 31;
    if (warp >= NSn * NKn) return;
    const float* src = keys + (size_t)warp * KDn;
    float* dst = g_knorm + (size_t)warp * KDn;
    float v0 = src[lane], v1 = src[lane + 32];
    float sq = v0 * v0 + v1 * v1;
#pragma unroll
    for (int o = 16; o > 0; o >>= 1) sq += __shfl_xor_sync(0xffffffffu, sq, o);
    const float scale = rsqrtf(sq);
    dst[lane]      = v0 * scale;
    dst[lane + 32] = v1 * scale;
}

// ---------------------------------------------------------------------------
// Fused scores -> top-8 -> softmax -> V gather, accumulating into g_att.
// Block: 128 threads = 128 tokens, one slot. Grid: (16 token tiles, 16 slots).
// Each thread keeps its q row (64) in registers and streams key tiles (32x64)
// through smem (broadcast reads), maintaining a sorted top-8 list.
// ---------------------------------------------------------------------------
__global__ void attn_kernel(const float* __restrict__ values)
{
    __shared__ float ksm[32][64];      // 8 KB key tile

    const int slot  = blockIdx.y;
    const int token = blockIdx.x * 128 + threadIdx.x;
    const int row   = token * NQn + slot;

    // q row -> registers
    float qr[64];
    {
        const float4* qp = (const float4*)(g_q + (size_t)row * KDn);
#pragma unroll
        for (int i = 0; i < 16; ++i) {
            float4 t = qp[i];
            qr[4 * i + 0] = t.x; qr[4 * i + 1] = t.y;
            qr[4 * i + 2] = t.z; qr[4 * i + 3] = t.w;
        }
    }

    float tv[8]; int ti[8];
#pragma unroll
    for (int i = 0; i < 8; ++i) { tv[i] = -FLT_MAX; ti[i] = 0; }

    const float* kbase = g_knorm + (size_t)(slot & 7) * NKn * KDn;

    for (int j0 = 0; j0 < NKn; j0 += 32) {
        // cooperative tile load: 32 keys x 64 dims = 512 float4
        const float4* src = (const float4*)(kbase + (size_t)j0 * KDn);
        float4* dst = (float4*)&ksm[0][0];
#pragma unroll
        for (int i = 0; i < 4; ++i)
            dst[threadIdx.x + 128 * i] = src[threadIdx.x + 128 * i];
        __syncthreads();

#pragma unroll 2
        for (int j = 0; j < 32; ++j) {
            const float4* kk = (const float4*)&ksm[j][0];
            float s = 0.f;
#pragma unroll
            for (int d = 0; d < 16; ++d) {
                float4 kv = kk[d];   // broadcast across the block
                s += qr[4 * d + 0] * kv.x + qr[4 * d + 1] * kv.y
                   + qr[4 * d + 2] * kv.z + qr[4 * d + 3] * kv.w;
            }
            if (s > tv[7]) {                 // strict >: earlier index wins ties
                tv[7] = s; ti[7] = j0 + j;   // insert then bubble up (list stays sorted desc)
#pragma unroll
                for (int p = 7; p > 0; --p) {
                    if (tv[p] > tv[p - 1]) {
                        float fv = tv[p]; tv[p] = tv[p - 1]; tv[p - 1] = fv;
                        int   iv = ti[p]; ti[p] = ti[p - 1]; ti[p - 1] = iv;
                    }
                }
            }
        }
        __syncthreads();
    }

    // softmax over the 8 kept scores (all others underflow to exactly 0)
    const float m = tv[0];
    float p[8], denom = 0.f;
#pragma unroll
    for (int i = 0; i < 8; ++i) { p[i] = expf(tv[i] - m); denom += p[i]; }
    const float inv = 1.f / denom;
#pragma unroll
    for (int i = 0; i < 8; ++i) p[i] *= inv;

    // gather top-8 value rows, accumulate into residual already in g_att
    const float* vbase = values + (size_t)(slot & 7) * NKn * VDn;
    float* arow = g_att + (size_t)row * VDn;
#pragma unroll
    for (int d0 = 0; d0 < VDn; d0 += 4) {
        float4 acc = *(float4*)&arow[d0];
#pragma unroll
        for (int i = 0; i < 8; ++i) {
            const float4 vv = *(const float4*)&vbase[(size_t)ti[i] * VDn + d0];
            acc.x += p[i] * vv.x; acc.y += p[i] * vv.y;
            acc.z += p[i] * vv.z; acc.w += p[i] * vv.w;
        }
        *(float4*)&arow[d0] = acc;
    }
}

// ---------------------------------------------------------------------------
// Host launcher (graph-capturable: kernel launches only, default stream)
// Inputs: 0:x 1:Wq 2:bq 3:ln_g 4:ln_b 5:keys 6:values 7:Wres 8:bres 9:Wmem 10:bmem
// ---------------------------------------------------------------------------
extern "C" void kernel_launch(void* const* d_in, const int* in_sizes, int n_in,
                              void* d_out, int out_size)
{
    const float* x      = (const float*)d_in[0];
    const float* Wq     = (const float*)d_in[1];
    const float* bq     = (const float*)d_in[2];
    const float* ln_g   = (const float*)d_in[3];
    const float* ln_b   = (const float*)d_in[4];
    const float* keys   = (const float*)d_in[5];
    const float* values = (const float*)d_in[6];
    const float* Wres   = (const float*)d_in[7];
    const float* bres   = (const float*)d_in[8];
    const float* Wmem   = (const float*)d_in[9];
    const float* bmem   = (const float*)d_in[10];
    float* out = (float*)d_out;

    // 1) q = x @ Wq + bq                     (2048 x 1024, K=512)
    gemm_q_kernel<<<dim3(16, 32), 256>>>(x, Wq, bq);
    // 2) in-place LayerNorm over rows of 64  (32768 rows)
    ln_kernel<<<4096, 256>>>(ln_g, ln_b);
    // 3) normalized keys                     (16384 rows)
    knorm_kernel<<<2048, 256>>>(keys);
    // 4) residual: g_att = q @ Wres + bres   (32768 x 128, K=64)
    gemm_res_kernel<<<dim3(2, 512), 256>>>(Wres, bres);
    // 5) fused top-8 attention, accumulate into g_att
    attn_kernel<<<dim3(16, 16), 128>>>(values);
    // 6) out = g_att @ Wmem + bmem, rows scattered into split layout
    gemm_out_kernel<<<dim3(8, 512), 256>>>(Wmem, bmem, out);
}

// round 2
// speedup vs baseline: 1.3077x; 1.3077x over previous
#include <cuda_runtime.h>
#include <cuda_bf16.h>
#include <math.h>
#include <float.h>

// Problem constants
#define BS_TOK 2048          // B*S
#define NQn 16               // query slots
#define NSn 8                // key/value slots
#define KDn 64
#define NKn 2048
#define VDn 128
#define MEMn 512
#define LN_EPS 1e-5f

// ---------------------------------------------------------------------------
// Scratch (static device globals; runtime allocation forbidden)
// ---------------------------------------------------------------------------
__device__ float          g_qraw[BS_TOK * NQn * KDn];     // pre-LN q (fp32)
__device__ float          g_att [BS_TOK * NQn * VDn];     // residual + attention (fp32)

__device__ __nv_bfloat16  g_xhi[BS_TOK * 512],      g_xlo[BS_TOK * 512];
__device__ __nv_bfloat16  g_wqhi[512 * NQn * KDn],  g_wqlo[512 * NQn * KDn];
__device__ __nv_bfloat16  g_qhi[BS_TOK * NQn * KDn], g_qlo[BS_TOK * NQn * KDn];
__device__ __nv_bfloat16  g_khi[NSn * NKn * KDn],    g_klo[NSn * NKn * KDn];
__device__ __nv_bfloat16  g_wreshi[KDn * VDn],       g_wreslo[KDn * VDn];
__device__ __nv_bfloat16  g_wmemhi[VDn * MEMn],      g_wmemlo[VDn * MEMn];
__device__ __nv_bfloat16  g_atthi[BS_TOK * NQn * VDn], g_attlo[BS_TOK * NQn * VDn];

// ---------------------------------------------------------------------------
// bf16 split helpers
// ---------------------------------------------------------------------------
__device__ __forceinline__ void split_bf16(float v, __nv_bfloat16& h, __nv_bfloat16& l)
{
    h = __float2bfloat16(v);
    l = __float2bfloat16(v - __bfloat162float(h));
}

__device__ __forceinline__ void mma16816(float c[4], const unsigned a[4], const unsigned b[2])
{
    asm("mma.sync.aligned.m16n8k16.row.col.f32.bf16.bf16.f32 "
        "{%0,%1,%2,%3},{%4,%5,%6,%7},{%8,%9},{%0,%1,%2,%3};"
        : "+f"(c[0]), "+f"(c[1]), "+f"(c[2]), "+f"(c[3])
        : "r"(a[0]), "r"(a[1]), "r"(a[2]), "r"(a[3]), "r"(b[0]), "r"(b[1]));
}

// ---------------------------------------------------------------------------
// Elementwise fp32 -> (hi, lo) bf16 split
// ---------------------------------------------------------------------------
__global__ void split_kernel(const float* __restrict__ in,
                             __nv_bfloat16* __restrict__ hi,
                             __nv_bfloat16* __restrict__ lo, int n)
{
    int i = blockIdx.x * blockDim.x + threadIdx.x;
    if (i < n) {
        float v = in[i];
        __nv_bfloat16 h, l;
        split_bf16(v, h, l);
        hi[i] = h; lo[i] = l;
    }
}

// ---------------------------------------------------------------------------
// Split-precision bf16 MMA GEMM: C = A(MxK) @ B(KxN) + bias  (fp32 result)
// A,B given as hi/lo bf16 pairs. Block tile 64x64, 4 warps (2x2), warp 32x32.
// K-chunk 32. M%64==0, N%64==0, K%32==0.
// ---------------------------------------------------------------------------
template<bool REMAP>
__global__ __launch_bounds__(128) void mma_gemm(const __nv_bfloat16* __restrict__ Ahi,
                                                const __nv_bfloat16* __restrict__ Alo,
                                                const __nv_bfloat16* __restrict__ Bhi,
                                                const __nv_bfloat16* __restrict__ Blo,
                                                const float* __restrict__ bias,
                                                float* __restrict__ C,
                                                int M, int N, int K)
{
    __shared__ __nv_bfloat16 sAh[64][36], sAl[64][36];
    __shared__ __nv_bfloat16 sBh[64][36], sBl[64][36];   // stored transposed: [n][k]

    const int tid  = threadIdx.x;
    const int lane = tid & 31;
    const int w    = tid >> 5;
    const int wm   = w >> 1, wn = w & 1;
    const int m0   = blockIdx.y << 6;
    const int n0   = blockIdx.x << 6;

    float c[2][4][4];
#pragma unroll
    for (int mt = 0; mt < 2; ++mt)
#pragma unroll
        for (int nt = 0; nt < 4; ++nt)
#pragma unroll
            for (int j = 0; j < 4; ++j) c[mt][nt][j] = 0.f;

    for (int k0 = 0; k0 < K; k0 += 32) {
        // A: 64 rows x 32 k, bf16 pairs as u32 (1024 u32 / array)
#pragma unroll
        for (int it = 0; it < 8; ++it) {
            int idx = it * 128 + tid;
            int r = idx >> 4, p = idx & 15;
            size_t g = (size_t)(m0 + r) * K + k0 + p * 2;
            *(unsigned*)&sAh[r][p * 2] = *(const unsigned*)(Ahi + g);
            *(unsigned*)&sAl[r][p * 2] = *(const unsigned*)(Alo + g);
        }
        // B: 32 k x 64 n, transposed into [n][k]
#pragma unroll
        for (int it = 0; it < 16; ++it) {
            int idx = it * 128 + tid;
            int k = idx >> 6, n = idx & 63;
            size_t g = (size_t)(k0 + k) * N + n0 + n;
            sBh[n][k] = Bhi[g];
            sBl[n][k] = Blo[g];
        }
        __syncthreads();

#pragma unroll
        for (int ks = 0; ks < 2; ++ks) {
            const int kk = ks * 16 + (lane & 3) * 2;
            unsigned bh[4][2], bl[4][2];
#pragma unroll
            for (int nt = 0; nt < 4; ++nt) {
                int nb = wn * 32 + nt * 8 + (lane >> 2);
                bh[nt][0] = *(const unsigned*)&sBh[nb][kk];
                bh[nt][1] = *(const unsigned*)&sBh[nb][kk + 8];
                bl[nt][0] = *(const unsigned*)&sBl[nb][kk];
                bl[nt][1] = *(const unsigned*)&sBl[nb][kk + 8];
            }
#pragma unroll
            for (int mt = 0; mt < 2; ++mt) {
                int rb = wm * 32 + mt * 16 + (lane >> 2);
                unsigned ah[4], al[4];
                ah[0] = *(const unsigned*)&sAh[rb][kk];
                ah[1] = *(const unsigned*)&sAh[rb + 8][kk];
                ah[2] = *(const unsigned*)&sAh[rb][kk + 8];
                ah[3] = *(const unsigned*)&sAh[rb + 8][kk + 8];
                al[0] = *(const unsigned*)&sAl[rb][kk];
                al[1] = *(const unsigned*)&sAl[rb + 8][kk];
                al[2] = *(const unsigned*)&sAl[rb][kk + 8];
                al[3] = *(const unsigned*)&sAl[rb + 8][kk + 8];
#pragma unroll
                for (int nt = 0; nt < 4; ++nt) {
                    mma16816(c[mt][nt], ah, bh[nt]);   // hi*hi
                    mma16816(c[mt][nt], ah, bl[nt]);   // hi*lo
                    mma16816(c[mt][nt], al, bh[nt]);   // lo*hi
                }
            }
        }
        __syncthreads();
    }

    // Epilogue
#pragma unroll
    for (int mt = 0; mt < 2; ++mt) {
#pragma unroll
        for (int nt = 0; nt < 4; ++nt) {
#pragma unroll
            for (int j = 0; j < 4; ++j) {
                int r   = m0 + wm * 32 + mt * 16 + (lane >> 2) + (j >= 2 ? 8 : 0);
                int col = n0 + wn * 32 + nt * 8 + (lane & 3) * 2 + (j & 1);
                float v = c[mt][nt][j] + bias[col];
                if (REMAP) {
                    const int token = r >> 4;
                    const int slot  = r & 15;
                    const size_t base = (slot < NSn) ? 0 : (size_t)BS_TOK * NSn * MEMn;
                    C[base + (size_t)(token * NSn + (slot & 7)) * MEMn + col] = v;
                } else {
                    C[(size_t)r * N + col] = v;
                }
            }
        }
    }
}

// ---------------------------------------------------------------------------
// LayerNorm over rows of 64 (reads g_qraw), emits hi/lo bf16 split
// ---------------------------------------------------------------------------
__global__ void ln_split_kernel(const float* __restrict__ gamma,
                                const float* __restrict__ beta)
{
    const int warp = (blockIdx.x * blockDim.x + threadIdx.x) >> 5;
    const int lane = threadIdx.x & 31;
    if (warp >= BS_TOK * NQn) return;
    const float* row = g_qraw + (size_t)warp * KDn;
    float v0 = row[lane], v1 = row[lane + 32];
    float s = v0 + v1;
#pragma unroll
    for (int o = 16; o > 0; o >>= 1) s += __shfl_xor_sync(0xffffffffu, s, o);
    const float mu = s * (1.f / 64.f);
    const float d0 = v0 - mu, d1 = v1 - mu;
    float sq = d0 * d0 + d1 * d1;
#pragma unroll
    for (int o = 16; o > 0; o >>= 1) sq += __shfl_xor_sync(0xffffffffu, sq, o);
    const float inv = rsqrtf(sq * (1.f / 64.f) + LN_EPS);
    float o0 = d0 * inv * gamma[lane]      + beta[lane];
    float o1 = d1 * inv * gamma[lane + 32] + beta[lane + 32];
    __nv_bfloat16 h, l;
    split_bf16(o0, h, l); g_qhi[(size_t)warp * KDn + lane] = h;      g_qlo[(size_t)warp * KDn + lane] = l;
    split_bf16(o1, h, l); g_qhi[(size_t)warp * KDn + lane + 32] = h; g_qlo[(size_t)warp * KDn + lane + 32] = l;
}

// ---------------------------------------------------------------------------
// L2-normalize key rows, emit hi/lo bf16
// ---------------------------------------------------------------------------
__global__ void knorm_split_kernel(const float* __restrict__ keys)
{
    const int warp = (blockIdx.x * blockDim.x + threadIdx.x) >> 5;
    const int lane = threadIdx.x & 31;
    if (warp >= NSn * NKn) return;
    const float* src = keys + (size_t)warp * KDn;
    float v0 = src[lane], v1 = src[lane + 32];
    float sq = v0 * v0 + v1 * v1;
#pragma unroll
    for (int o = 16; o > 0; o >>= 1) sq += __shfl_xor_sync(0xffffffffu, sq, o);
    const float scale = rsqrtf(sq);
    __nv_bfloat16 h, l;
    split_bf16(v0 * scale, h, l); g_khi[(size_t)warp * KDn + lane] = h;      g_klo[(size_t)warp * KDn + lane] = l;
    split_bf16(v1 * scale, h, l); g_khi[(size_t)warp * KDn + lane + 32] = h; g_klo[(size_t)warp * KDn + lane + 32] = l;
}

// ---------------------------------------------------------------------------
// Fused scores (split-bf16 MMA) -> top-8 -> softmax -> V gather, += g_att.
// Block: 128 threads (4 warps), 64 tokens, 1 slot. Grid (32 token tiles, 16 slots).
// Key chunks of 32; scores tile in smem; 2 threads/token keep running top-8.
// ---------------------------------------------------------------------------
__global__ __launch_bounds__(128) void attn_mma_kernel(const float* __restrict__ values)
{
    __shared__ __nv_bfloat16 sQh[64][66], sQl[64][66];
    __shared__ __nv_bfloat16 sKh[32][66], sKl[32][66];
    __shared__ float sc[64][33];
    __shared__ float mgv[64][16];
    __shared__ int   mgi[64][16];
    __shared__ float pw[64][8];
    __shared__ int   pidx[64][8];

    const int tid  = threadIdx.x;
    const int lane = tid & 31;
    const int w    = tid >> 5;
    const int slot = blockIdx.y;
    const int t0   = blockIdx.x * 64;

    // Load q tile (64 tokens x 64 dims), row = (token*16 + slot)
#pragma unroll
    for (int it = 0; it < 16; ++it) {
        int idx = it * 128 + tid;
        int r = idx >> 5, p = idx & 31;
        size_t g = ((size_t)(t0 + r) * NQn + slot) * KDn + p * 2;
        *(unsigned*)&sQh[r][p * 2] = *(const unsigned*)(g_qhi + g);
        *(unsigned*)&sQl[r][p * 2] = *(const unsigned*)(g_qlo + g);
    }

    float tv[8]; int ti[8];
#pragma unroll
    for (int i = 0; i < 8; ++i) { tv[i] = -FLT_MAX; ti[i] = 0; }

    const __nv_bfloat16* kbh = g_khi + (size_t)(slot & 7) * NKn * KDn;
    const __nv_bfloat16* kbl = g_klo + (size_t)(slot & 7) * NKn * KDn;

    for (int ch = 0; ch < 64; ++ch) {
        // Load 32-key chunk
#pragma unroll
        for (int it = 0; it < 8; ++it) {
            int idx = it * 128 + tid;
            int r = idx >> 5, p = idx & 31;
            size_t g = (size_t)(ch * 32 + r) * KDn + p * 2;
            *(unsigned*)&sKh[r][p * 2] = *(const unsigned*)(kbh + g);
            *(unsigned*)&sKl[r][p * 2] = *(const unsigned*)(kbl + g);
        }
        __syncthreads();  // K tile ready; prior scan done (scan precedes loads per-warp)

        float c[4][4];
#pragma unroll
        for (int nt = 0; nt < 4; ++nt)
#pragma unroll
            for (int j = 0; j < 4; ++j) c[nt][j] = 0.f;

#pragma unroll
        for (int ks = 0; ks < 4; ++ks) {
            const int kk = ks * 16 + (lane & 3) * 2;
            const int rb = w * 16 + (lane >> 2);
            unsigned ah[4], al[4];
            ah[0] = *(const unsigned*)&sQh[rb][kk];
            ah[1] = *(const unsigned*)&sQh[rb + 8][kk];
            ah[2] = *(const unsigned*)&sQh[rb][kk + 8];
            ah[3] = *(const unsigned*)&sQh[rb + 8][kk + 8];
            al[0] = *(const unsigned*)&sQl[rb][kk];
            al[1] = *(const unsigned*)&sQl[rb + 8][kk];
            al[2] = *(const unsigned*)&sQl[rb][kk + 8];
            al[3] = *(const unsigned*)&sQl[rb + 8][kk + 8];
#pragma unroll
            for (int nt = 0; nt < 4; ++nt) {
                int nb = nt * 8 + (lane >> 2);
                unsigned bh[2], bl[2];
                bh[0] = *(const unsigned*)&sKh[nb][kk];
                bh[1] = *(const unsigned*)&sKh[nb][kk + 8];
                bl[0] = *(const unsigned*)&sKl[nb][kk];
                bl[1] = *(const unsigned*)&sKl[nb][kk + 8];
                mma16816(c[nt], ah, bh);
                mma16816(c[nt], ah, bl);
                mma16816(c[nt], al, bh);
            }
        }

        // Scores -> smem
        {
            const int r  = w * 16 + (lane >> 2);
#pragma unroll
            for (int nt = 0; nt < 4; ++nt) {
                const int cb = nt * 8 + (lane & 3) * 2;
                sc[r][cb]         = c[nt][0];
                sc[r][cb + 1]     = c[nt][1];
                sc[r + 8][cb]     = c[nt][2];
                sc[r + 8][cb + 1] = c[nt][3];
            }
        }
        __syncthreads();  // scores visible

        // Running top-8 scan: 2 threads/token, 16 keys each
        {
            const int t = tid >> 1, base = (tid & 1) * 16;
#pragma unroll
            for (int j = 0; j < 16; ++j) {
                float s = sc[t][base + j];
                if (s > tv[7]) {
                    tv[7] = s; ti[7] = ch * 32 + base + j;
#pragma unroll
                    for (int p = 7; p > 0; --p) {
                        if (tv[p] > tv[p - 1]) {
                            float fv = tv[p]; tv[p] = tv[p - 1]; tv[p - 1] = fv;
                            int   iv = ti[p]; ti[p] = ti[p - 1]; ti[p - 1] = iv;
                        }
                    }
                }
            }
        }
        // no sync needed here: next loop writes sKh (disjoint from sc),
        // and the top-of-loop sync orders scan vs next score write
    }

    // Merge the two per-token runs
    {
        const int t = tid >> 1, half = tid & 1;
#pragma unroll
        for (int i = 0; i < 8; ++i) { mgv[t][half * 8 + i] = tv[i]; mgi[t][half * 8 + i] = ti[i]; }
    }
    __syncthreads();

    if (tid < 64) {
        const int t = tid;
        float mv[8]; int mi[8];
        int ia = 0, ib = 8;
#pragma unroll
        for (int s = 0; s < 8; ++s) {
            float v1 = (ia < 8)  ? mgv[t][ia] : -FLT_MAX;
            float v2 = (ib < 16) ? mgv[t][ib] : -FLT_MAX;
            if (v1 >= v2) { mv[s] = v1; mi[s] = mgi[t][ia]; ++ia; }
            else          { mv[s] = v2; mi[s] = mgi[t][ib]; ++ib; }
        }
        const float m = mv[0];
        float p[8], denom = 0.f;
#pragma unroll
        for (int i = 0; i < 8; ++i) { p[i] = expf(mv[i] - m); denom += p[i]; }
        const float inv = 1.f / denom;
#pragma unroll
        for (int i = 0; i < 8; ++i) { pw[t][i] = p[i] * inv; pidx[t][i] = mi[i]; }
    }
    __syncthreads();

    // V gather: 2 threads/token, 64 dims each; accumulate into residual in g_att
    {
        const int t  = tid >> 1;
        const int d0 = (tid & 1) * 64;
        float pr[8]; int ir[8];
#pragma unroll
        for (int i = 0; i < 8; ++i) { pr[i] = pw[t][i]; ir[i] = pidx[t][i]; }
        const size_t row = (size_t)(t0 + t) * NQn + slot;
        float* ar = g_att + row * VDn + d0;
        const float* vb = values + (size_t)(slot & 7) * NKn * VDn + d0;
#pragma unroll
        for (int dd = 0; dd < 64; dd += 4) {
            float4 acc = *(float4*)(ar + dd);
#pragma unroll
            for (int i = 0; i < 8; ++i) {
                const float4 vv = *(const float4*)(vb + (size_t)ir[i] * VDn + dd);
                acc.x += pr[i] * vv.x; acc.y += pr[i] * vv.y;
                acc.z += pr[i] * vv.z; acc.w += pr[i] * vv.w;
            }
            *(float4*)(ar + dd) = acc;
        }
    }
}

// ---------------------------------------------------------------------------
// Host launcher (graph-capturable)
// Inputs: 0:x 1:Wq 2:bq 3:ln_g 4:ln_b 5:keys 6:values 7:Wres 8:bres 9:Wmem 10:bmem
// ---------------------------------------------------------------------------
extern "C" void kernel_launch(void* const* d_in, const int* in_sizes, int n_in,
                              void* d_out, int out_size)
{
    const float* x      = (const float*)d_in[0];
    const float* Wq     = (const float*)d_in[1];
    const float* bq     = (const float*)d_in[2];
    const float* ln_g   = (const float*)d_in[3];
    const float* ln_b   = (const float*)d_in[4];
    const float* keys   = (const float*)d_in[5];
    const float* values = (const float*)d_in[6];
    const float* Wres   = (const float*)d_in[7];
    const float* bres   = (const float*)d_in[8];
    const float* Wmem   = (const float*)d_in[9];
    const float* bmem   = (const float*)d_in[10];
    float* out = (float*)d_out;

    __nv_bfloat16 *xhi, *xlo, *wqhi, *wqlo, *qhi, *qlo;
    __nv_bfloat16 *wreshi, *wreslo, *wmemhi, *wmemlo, *atthi, *attlo;
    float *qraw, *att;
    cudaGetSymbolAddress((void**)&xhi,    g_xhi);    cudaGetSymbolAddress((void**)&xlo,    g_xlo);
    cudaGetSymbolAddress((void**)&wqhi,   g_wqhi);   cudaGetSymbolAddress((void**)&wqlo,   g_wqlo);
    cudaGetSymbolAddress((void**)&qhi,    g_qhi);    cudaGetSymbolAddress((void**)&qlo,    g_qlo);
    cudaGetSymbolAddress((void**)&wreshi, g_wreshi); cudaGetSymbolAddress((void**)&wreslo, g_wreslo);
    cudaGetSymbolAddress((void**)&wmemhi, g_wmemhi); cudaGetSymbolAddress((void**)&wmemlo, g_wmemlo);
    cudaGetSymbolAddress((void**)&atthi,  g_atthi);  cudaGetSymbolAddress((void**)&attlo,  g_attlo);
    cudaGetSymbolAddress((void**)&qraw,   g_qraw);   cudaGetSymbolAddress((void**)&att,    g_att);

    // Split inputs to bf16 hi/lo
    split_kernel<<<(BS_TOK * 512 + 255) / 256, 256>>>(x,    xhi,    xlo,    BS_TOK * 512);
    split_kernel<<<(512 * NQn * KDn + 255) / 256, 256>>>(Wq, wqhi,   wqlo,   512 * NQn * KDn);
    split_kernel<<<(KDn * VDn + 255) / 256, 256>>>(Wres,    wreshi, wreslo, KDn * VDn);
    split_kernel<<<(VDn * MEMn + 255) / 256, 256>>>(Wmem,   wmemhi, wmemlo, VDn * MEMn);

    // 1) q = x @ Wq + bq  (2048 x 1024, K=512)
    mma_gemm<false><<<dim3(16, 32), 128>>>(xhi, xlo, wqhi, wqlo, bq, qraw, BS_TOK, NQn * KDn, 512);
    // 2) LayerNorm rows of 64 -> q hi/lo
    ln_split_kernel<<<4096, 256>>>(ln_g, ln_b);
    // 3) normalized keys -> hi/lo
    knorm_split_kernel<<<2048, 256>>>(keys);
    // 4) residual: g_att = q @ Wres + bres  (32768 x 128, K=64)
    mma_gemm<false><<<dim3(2, 512), 128>>>(qhi, qlo, wreshi, wreslo, bres, att,
                                           BS_TOK * NQn, VDn, KDn);
    // 5) fused scores -> top-8 -> softmax -> gather, += g_att
    attn_mma_kernel<<<dim3(32, 16), 128>>>(values);
    // 6) split g_att, then out = g_att @ Wmem + bmem (REMAP to split layout)
    split_kernel<<<(BS_TOK * NQn * VDn + 255) / 256, 256>>>(att, atthi, attlo, BS_TOK * NQn * VDn);
    mma_gemm<true><<<dim3(8, 512), 128>>>(atthi, attlo, wmemhi, wmemlo, bmem, out,
                                          BS_TOK * NQn, MEMn, VDn);
}

// round 4
// speedup vs baseline: 1.5977x; 1.2218x over previous
#include <cuda_runtime.h>
#include <cuda_bf16.h>
#include <math.h>
#include <float.h>
#include <stdint.h>

// Problem constants
#define BS_TOK 2048
#define NQn 16
#define NSn 8
#define KDn 64
#define NKn 2048
#define VDn 128
#define MEMn 512
#define LN_EPS 1e-5f

// ---------------------------------------------------------------------------
// Scratch globals
// ---------------------------------------------------------------------------
__device__ float         g_qraw[BS_TOK * NQn * KDn];
__device__ float         g_att [BS_TOK * NQn * VDn];          // residual (fp32)

__device__ __nv_bfloat16 g_xhi[BS_TOK * 512],        g_xlo[BS_TOK * 512];
__device__ __nv_bfloat16 g_wqt_hi[1024 * 512],       g_wqt_lo[1024 * 512];    // Wq^T  [N][K]
__device__ __nv_bfloat16 g_qhi[BS_TOK * NQn * KDn],  g_qlo[BS_TOK * NQn * KDn];
__device__ __nv_bfloat16 g_khi[NSn * NKn * KDn],     g_klo[NSn * NKn * KDn];
__device__ __nv_bfloat16 g_wrest_hi[VDn * KDn],      g_wrest_lo[VDn * KDn];   // Wres^T [128][64]
__device__ __nv_bfloat16 g_wmemt_hi[MEMn * VDn],     g_wmemt_lo[MEMn * VDn];  // Wmem^T [512][128]
__device__ __nv_bfloat16 g_atthi[BS_TOK * NQn * VDn], g_attlo[BS_TOK * NQn * VDn];

// ---------------------------------------------------------------------------
// Helpers
// ---------------------------------------------------------------------------
__device__ __forceinline__ uint32_t smem_u32(const void* p) {
    uint32_t a;
    asm("{ .reg .u64 t; cvta.to.shared.u64 t, %1; cvt.u32.u64 %0, t; }" : "=r"(a) : "l"(p));
    return a;
}
__device__ __forceinline__ uint32_t sw128(uint32_t off) { return off ^ ((off >> 3) & 0x70); }

__device__ __forceinline__ void mma16816(float c[4], const uint32_t a[4], const uint32_t b[2])
{
    asm("mma.sync.aligned.m16n8k16.row.col.f32.bf16.bf16.f32 "
        "{%0,%1,%2,%3},{%4,%5,%6,%7},{%8,%9},{%0,%1,%2,%3};"
        : "+f"(c[0]), "+f"(c[1]), "+f"(c[2]), "+f"(c[3])
        : "r"(a[0]), "r"(a[1]), "r"(a[2]), "r"(a[3]), "r"(b[0]), "r"(b[1]));
}
__device__ __forceinline__ void ldsm4(uint32_t& r0, uint32_t& r1, uint32_t& r2, uint32_t& r3, uint32_t addr)
{
    asm volatile("ldmatrix.sync.aligned.m8n8.x4.shared.b16 {%0,%1,%2,%3}, [%4];"
                 : "=r"(r0), "=r"(r1), "=r"(r2), "=r"(r3) : "r"(addr));
}
__device__ __forceinline__ void split_bf16(float v, __nv_bfloat16& h, __nv_bfloat16& l) {
    h = __float2bfloat16(v);
    l = __float2bfloat16(v - __bfloat162float(h));
}

// ---------------------------------------------------------------------------
// Prep kernels
// ---------------------------------------------------------------------------
__global__ void split_kernel(const float* __restrict__ in,
                             __nv_bfloat16* __restrict__ hi,
                             __nv_bfloat16* __restrict__ lo, int n)
{
    int i = blockIdx.x * blockDim.x + threadIdx.x;
    if (i < n) {
        __nv_bfloat16 h, l;
        split_bf16(in[i], h, l);
        hi[i] = h; lo[i] = l;
    }
}

// in: (K, N) row-major -> out hi/lo: (N, K) row-major
__global__ void tsplit_kernel(const float* __restrict__ in,
                              __nv_bfloat16* __restrict__ hi,
                              __nv_bfloat16* __restrict__ lo, int K, int N)
{
    int i = blockIdx.x * blockDim.x + threadIdx.x;
    if (i < K * N) {
        int k = i / N, n = i % N;
        __nv_bfloat16 h, l;
        split_bf16(in[i], h, l);
        hi[(size_t)n * K + k] = h;
        lo[(size_t)n * K + k] = l;
    }
}

__global__ void ln_split_kernel(const float* __restrict__ gamma,
                                const float* __restrict__ beta)
{
    const int warp = (blockIdx.x * blockDim.x + threadIdx.x) >> 5;
    const int lane = threadIdx.x & 31;
    if (warp >= BS_TOK * NQn) return;
    const float* row = g_qraw + (size_t)warp * KDn;
    float v0 = row[lane], v1 = row[lane + 32];
    float s = v0 + v1;
#pragma unroll
    for (int o = 16; o > 0; o >>= 1) s += __shfl_xor_sync(0xffffffffu, s, o);
    const float mu = s * (1.f / 64.f);
    const float d0 = v0 - mu, d1 = v1 - mu;
    float sq = d0 * d0 + d1 * d1;
#pragma unroll
    for (int o = 16; o > 0; o >>= 1) sq += __shfl_xor_sync(0xffffffffu, sq, o);
    const float inv = rsqrtf(sq * (1.f / 64.f) + LN_EPS);
    float o0 = d0 * inv * gamma[lane] + beta[lane];
    float o1 = d1 * inv * gamma[lane + 32] + beta[lane + 32];
    __nv_bfloat16 h, l;
    split_bf16(o0, h, l); g_qhi[(size_t)warp * KDn + lane] = h;      g_qlo[(size_t)warp * KDn + lane] = l;
    split_bf16(o1, h, l); g_qhi[(size_t)warp * KDn + lane + 32] = h; g_qlo[(size_t)warp * KDn + lane + 32] = l;
}

__global__ void knorm_split_kernel(const float* __restrict__ keys)
{
    const int warp = (blockIdx.x * blockDim.x + threadIdx.x) >> 5;
    const int lane = threadIdx.x & 31;
    if (warp >= NSn * NKn) return;
    const float* src = keys + (size_t)warp * KDn;
    float v0 = src[lane], v1 = src[lane + 32];
    float sq = v0 * v0 + v1 * v1;
#pragma unroll
    for (int o = 16; o > 0; o >>= 1) sq += __shfl_xor_sync(0xffffffffu, sq, o);
    const float scale = rsqrtf(sq);
    __nv_bfloat16 h, l;
    split_bf16(v0 * scale, h, l); g_khi[(size_t)warp * KDn + lane] = h;      g_klo[(size_t)warp * KDn + lane] = l;
    split_bf16(v1 * scale, h, l); g_khi[(size_t)warp * KDn + lane + 32] = h; g_klo[(size_t)warp * KDn + lane + 32] = l;
}

// ---------------------------------------------------------------------------
// Split-bf16 MMA GEMM with ldmatrix. C[M,N] = A[M,K] @ Bt[N,K]^T + bias.
// Block tile 128x128, 8 warps (4 m x 2 n), warp tile 32x64, K-chunk 64.
// Smem rows: 64 bf16 = 128B, SW128 swizzled.
// ---------------------------------------------------------------------------
#define GSM_AH 0
#define GSM_AL 16384
#define GSM_BH 32768
#define GSM_BL 49152
#define GEMM_SMEM 65536

template<bool REMAP>
__global__ __launch_bounds__(256) void wm_gemm(const __nv_bfloat16* __restrict__ Ahi,
                                               const __nv_bfloat16* __restrict__ Alo,
                                               const __nv_bfloat16* __restrict__ Bhi,
                                               const __nv_bfloat16* __restrict__ Blo,
                                               const float* __restrict__ bias,
                                               float* __restrict__ C,
                                               int M, int N, int K)
{
    extern __shared__ char smem[];
    const uint32_t sb = smem_u32(smem);
    const int tid  = threadIdx.x;
    const int lane = tid & 31;
    const int w    = tid >> 5;
    const int wm   = w & 3;
    const int wn   = w >> 2;
    const int m0   = blockIdx.y << 7;
    const int n0   = blockIdx.x << 7;

    float c[2][8][4];
#pragma unroll
    for (int mt = 0; mt < 2; ++mt)
#pragma unroll
        for (int nt = 0; nt < 8; ++nt)
#pragma unroll
            for (int j = 0; j < 4; ++j) c[mt][nt][j] = 0.f;

    // ldmatrix source addresses (fixed per thread, add region base + ks offset)
    const uint32_t a_off0 = (uint32_t)((wm * 32 + (lane & 15)) * 128 + ((lane >> 4) << 4));
    const uint32_t a_off1 = (uint32_t)((wm * 32 + 16 + (lane & 15)) * 128 + ((lane >> 4) << 4));
    const uint32_t b_row  = (uint32_t)(wn * 64 + (lane & 7) + ((lane >> 4) << 3));
    const uint32_t b_coff = (uint32_t)(((lane >> 3) & 1) << 4);

    const int nch = K >> 6;
    for (int ch = 0; ch < nch; ++ch) {
        const int k0 = ch << 6;
        // Load A/B tiles: 128 rows x 128B each (1024 x 16B chunks per array)
        for (int it = tid; it < 1024; it += 256) {
            const int r = it >> 3, p = it & 7;
            const uint32_t off = sw128((uint32_t)(r * 128 + p * 16));
            const size_t ga = (size_t)(m0 + r) * K + k0 + p * 8;
            *(uint4*)(smem + GSM_AH + off) = *(const uint4*)(Ahi + ga);
            *(uint4*)(smem + GSM_AL + off) = *(const uint4*)(Alo + ga);
            const size_t gb = (size_t)(n0 + r) * K + k0 + p * 8;
            *(uint4*)(smem + GSM_BH + off) = *(const uint4*)(Bhi + gb);
            *(uint4*)(smem + GSM_BL + off) = *(const uint4*)(Blo + gb);
        }
        __syncthreads();

#pragma unroll
        for (int ks = 0; ks < 4; ++ks) {
            const uint32_t kof = (uint32_t)(ks * 32);
            uint32_t ah0[4], ah1[4], al0[4], al1[4];
            ldsm4(ah0[0], ah0[1], ah0[2], ah0[3], sb + GSM_AH + sw128(a_off0 + kof));
            ldsm4(ah1[0], ah1[1], ah1[2], ah1[3], sb + GSM_AH + sw128(a_off1 + kof));
            ldsm4(al0[0], al0[1], al0[2], al0[3], sb + GSM_AL + sw128(a_off0 + kof));
            ldsm4(al1[0], al1[1], al1[2], al1[3], sb + GSM_AL + sw128(a_off1 + kof));
#pragma unroll
            for (int p = 0; p < 4; ++p) {      // pairs of n8 tiles
                uint32_t bh[4], bl[4];
                const uint32_t boff = (uint32_t)((b_row + p * 16) * 128) + b_coff + kof;
                ldsm4(bh[0], bh[1], bh[2], bh[3], sb + GSM_BH + sw128(boff));
                ldsm4(bl[0], bl[1], bl[2], bl[3], sb + GSM_BL + sw128(boff));
                mma16816(c[0][2 * p],     ah0, bh);      mma16816(c[1][2 * p],     ah1, bh);
                mma16816(c[0][2 * p + 1], ah0, bh + 2);  mma16816(c[1][2 * p + 1], ah1, bh + 2);
                mma16816(c[0][2 * p],     ah0, bl);      mma16816(c[1][2 * p],     ah1, bl);
                mma16816(c[0][2 * p + 1], ah0, bl + 2);  mma16816(c[1][2 * p + 1], ah1, bl + 2);
                mma16816(c[0][2 * p],     al0, bh);      mma16816(c[1][2 * p],     al1, bh);
                mma16816(c[0][2 * p + 1], al0, bh + 2);  mma16816(c[1][2 * p + 1], al1, bh + 2);
            }
        }
        __syncthreads();
    }

    // Epilogue
#pragma unroll
    for (int mt = 0; mt < 2; ++mt) {
#pragma unroll
        for (int nt = 0; nt < 8; ++nt) {
#pragma unroll
            for (int j = 0; j < 4; ++j) {
                const int r   = m0 + wm * 32 + mt * 16 + (lane >> 2) + (j >= 2 ? 8 : 0);
                const int col = n0 + wn * 64 + nt * 8 + (lane & 3) * 2 + (j & 1);
                const float v = c[mt][nt][j] + __ldg(bias + col);
                if (REMAP) {
                    const int token = r >> 4;
                    const int slot  = r & 15;
                    const size_t base = (slot < NSn) ? 0 : (size_t)BS_TOK * NSn * MEMn;
                    C[base + (size_t)(token * NSn + (slot & 7)) * MEMn + col] = v;
                } else {
                    C[(size_t)r * N + col] = v;
                }
            }
        }
    }
}

// ---------------------------------------------------------------------------
// Fused attention: per (128-token tile, slot):
//   Q tile in smem once; 32 chunks of 64 keys; scores via split-bf16 MMA
//   (warp tile 32x32, 8 warps 4x2) -> smem score tile -> running per-thread
//   top-8 (2 threads/token) -> merge -> softmax -> V gather + residual
//   -> write hi/lo bf16 split of result for gemm_out.
// ---------------------------------------------------------------------------
#define ASM_QH 0
#define ASM_QL 16384
#define ASM_KH 32768
#define ASM_KL 40960
#define ASM_SC 49152                      // 128 x 65 fp32 = 33280 B
#define ATTN_SMEM (49152 + 33280)
#define SC_PITCH 65

__global__ __launch_bounds__(256) void attn_kernel(const float* __restrict__ values)
{
    extern __shared__ char smem[];
    float* sc = (float*)(smem + ASM_SC);
    const uint32_t sb = smem_u32(smem);
    const int tid  = threadIdx.x;
    const int lane = tid & 31;
    const int w    = tid >> 5;
    const int wm   = w & 3;
    const int wn   = w >> 2;
    const int slot = blockIdx.y;
    const int t0   = blockIdx.x << 7;

    // Q tile: 128 tokens x 64 bf16, hi/lo
    for (int it = tid; it < 1024; it += 256) {
        const int r = it >> 3, p = it & 7;
        const uint32_t off = sw128((uint32_t)(r * 128 + p * 16));
        const size_t g = ((size_t)(t0 + r) * NQn + slot) * KDn + p * 8;
        *(uint4*)(smem + ASM_QH + off) = *(const uint4*)(g_qhi + g);
        *(uint4*)(smem + ASM_QL + off) = *(const uint4*)(g_qlo + g);
    }

    const __nv_bfloat16* kbh = g_khi + (size_t)(slot & 7) * NKn * KDn;
    const __nv_bfloat16* kbl = g_klo + (size_t)(slot & 7) * NKn * KDn;

    const uint32_t a_off0 = (uint32_t)((wm * 32 + (lane & 15)) * 128 + ((lane >> 4) << 4));
    const uint32_t a_off1 = (uint32_t)((wm * 32 + 16 + (lane & 15)) * 128 + ((lane >> 4) << 4));
    const uint32_t b_row  = (uint32_t)(wn * 32 + (lane & 7) + ((lane >> 4) << 3));
    const uint32_t b_coff = (uint32_t)(((lane >> 3) & 1) << 4);

    float tv[8]; int ti[8];
#pragma unroll
    for (int i = 0; i < 8; ++i) { tv[i] = -FLT_MAX; ti[i] = 0; }

    for (int ch = 0; ch < 32; ++ch) {
        // K chunk: 64 keys x 64 bf16, hi/lo (512 x 16B per array)
        for (int it = tid; it < 512; it += 256) {
            const int r = it >> 3, p = it & 7;
            const uint32_t off = sw128((uint32_t)(r * 128 + p * 16));
            const size_t g = (size_t)(ch * 64 + r) * KDn + p * 8;
            *(uint4*)(smem + ASM_KH + off) = *(const uint4*)(kbh + g);
            *(uint4*)(smem + ASM_KL + off) = *(const uint4*)(kbl + g);
        }
        __syncthreads();   // K ready; previous scan done

        float c[2][4][4];
#pragma unroll
        for (int mt = 0; mt < 2; ++mt)
#pragma unroll
            for (int nt = 0; nt < 4; ++nt)
#pragma unroll
                for (int j = 0; j < 4; ++j) c[mt][nt][j] = 0.f;

#pragma unroll
        for (int ks = 0; ks < 4; ++ks) {
            const uint32_t kof = (uint32_t)(ks * 32);
            uint32_t ah0[4], ah1[4], al0[4], al1[4];
            ldsm4(ah0[0], ah0[1], ah0[2], ah0[3], sb + ASM_QH + sw128(a_off0 + kof));
            ldsm4(ah1[0], ah1[1], ah1[2], ah1[3], sb + ASM_QH + sw128(a_off1 + kof));
            ldsm4(al0[0], al0[1], al0[2], al0[3], sb + ASM_QL + sw128(a_off0 + kof));
            ldsm4(al1[0], al1[1], al1[2], al1[3], sb + ASM_QL + sw128(a_off1 + kof));
#pragma unroll
            for (int p = 0; p < 2; ++p) {
                uint32_t bh[4], bl[4];
                const uint32_t boff = (uint32_t)((b_row + p * 16) * 128) + b_coff + kof;
                ldsm4(bh[0], bh[1], bh[2], bh[3], sb + ASM_KH + sw128(boff));
                ldsm4(bl[0], bl[1], bl[2], bl[3], sb + ASM_KL + sw128(boff));
                mma16816(c[0][2 * p],     ah0, bh);      mma16816(c[1][2 * p],     ah1, bh);
                mma16816(c[0][2 * p + 1], ah0, bh + 2);  mma16816(c[1][2 * p + 1], ah1, bh + 2);
                mma16816(c[0][2 * p],     ah0, bl);      mma16816(c[1][2 * p],     ah1, bl);
                mma16816(c[0][2 * p + 1], ah0, bl + 2);  mma16816(c[1][2 * p + 1], ah1, bl + 2);
                mma16816(c[0][2 * p],     al0, bh);      mma16816(c[1][2 * p],     al1, bh);
                mma16816(c[0][2 * p + 1], al0, bh + 2);  mma16816(c[1][2 * p + 1], al1, bh + 2);
            }
        }

        // scores -> smem
#pragma unroll
        for (int mt = 0; mt < 2; ++mt) {
            const int r = wm * 32 + mt * 16 + (lane >> 2);
#pragma unroll
            for (int nt = 0; nt < 4; ++nt) {
                const int cb = wn * 32 + nt * 8 + (lane & 3) * 2;
                sc[r * SC_PITCH + cb]           = c[mt][nt][0];
                sc[r * SC_PITCH + cb + 1]       = c[mt][nt][1];
                sc[(r + 8) * SC_PITCH + cb]     = c[mt][nt][2];
                sc[(r + 8) * SC_PITCH + cb + 1] = c[mt][nt][3];
            }
        }
        __syncthreads();   // scores visible

        // running top-8: thread -> token tid>>1, keys (tid&1)*32 .. +31
        {
            const int t = tid >> 1, base = (tid & 1) * 32;
#pragma unroll
            for (int j = 0; j < 32; ++j) {
                const float s = sc[t * SC_PITCH + base + j];
                if (s > tv[7]) {
                    tv[7] = s; ti[7] = ch * 64 + base + j;
#pragma unroll
                    for (int p = 7; p > 0; --p) {
                        if (tv[p] > tv[p - 1]) {
                            float fv = tv[p]; tv[p] = tv[p - 1]; tv[p - 1] = fv;
                            int   iv = ti[p]; ti[p] = ti[p - 1]; ti[p - 1] = iv;
                        }
                    }
                }
            }
        }
        // next iteration's first sync orders scan completion vs score rewrite
    }
    __syncthreads();

    // merge 2 runs per token (reuse sc region)
    float* mgv = sc;                     // 128 x 16
    int*   mgi = (int*)(sc + 2048);      // 128 x 16
    float* pw  = (float*)(sc + 4096);    // 128 x 8
    int*   pidx = (int*)(sc + 5120);     // 128 x 8
    {
        const int t = tid >> 1, half = tid & 1;
#pragma unroll
        for (int i = 0; i < 8; ++i) { mgv[t * 16 + half * 8 + i] = tv[i]; mgi[t * 16 + half * 8 + i] = ti[i]; }
    }
    __syncthreads();

    if (tid < 128) {
        const int t = tid;
        float mv[8]; int mi[8];
        int ia = 0, ib = 8;
#pragma unroll
        for (int s = 0; s < 8; ++s) {
            float v1 = (ia < 8)  ? mgv[t * 16 + ia] : -FLT_MAX;
            float v2 = (ib < 16) ? mgv[t * 16 + ib] : -FLT_MAX;
            if (v1 >= v2) { mv[s] = v1; mi[s] = mgi[t * 16 + ia]; ++ia; }
            else          { mv[s] = v2; mi[s] = mgi[t * 16 + ib]; ++ib; }
        }
        const float m = mv[0];
        float p[8], denom = 0.f;
#pragma unroll
        for (int i = 0; i < 8; ++i) { p[i] = expf(mv[i] - m); denom += p[i]; }
        const float inv = 1.f / denom;
#pragma unroll
        for (int i = 0; i < 8; ++i) { pw[t * 8 + i] = p[i] * inv; pidx[t * 8 + i] = mi[i]; }
    }
    __syncthreads();

    // V gather + residual, write hi/lo split: 2 threads/token, 64 dims each
    {
        const int t  = tid >> 1;
        const int d0 = (tid & 1) * 64;
        float pr[8]; int ir[8];
#pragma unroll
        for (int i = 0; i < 8; ++i) { pr[i] = pw[t * 8 + i]; ir[i] = pidx[t * 8 + i]; }
        const size_t row = (size_t)(t0 + t) * NQn + slot;
        const float* resr = g_att + row * VDn + d0;
        const float* vb   = values + (size_t)(slot & 7) * NKn * VDn + d0;
        __nv_bfloat16* oh = g_atthi + row * VDn + d0;
        __nv_bfloat16* ol = g_attlo + row * VDn + d0;
#pragma unroll
        for (int dd = 0; dd < 64; dd += 4) {
            float4 acc = *(const float4*)(resr + dd);
#pragma unroll
            for (int i = 0; i < 8; ++i) {
                const float4 vv = *(const float4*)(vb + (size_t)ir[i] * VDn + dd);
                acc.x += pr[i] * vv.x; acc.y += pr[i] * vv.y;
                acc.z += pr[i] * vv.z; acc.w += pr[i] * vv.w;
            }
            __nv_bfloat16 h, l;
            split_bf16(acc.x, h, l); oh[dd]     = h; ol[dd]     = l;
            split_bf16(acc.y, h, l); oh[dd + 1] = h; ol[dd + 1] = l;
            split_bf16(acc.z, h, l); oh[dd + 2] = h; ol[dd + 2] = l;
            split_bf16(acc.w, h, l); oh[dd + 3] = h; ol[dd + 3] = l;
        }
    }
}

// ---------------------------------------------------------------------------
// Host launcher
// Inputs: 0:x 1:Wq 2:bq 3:ln_g 4:ln_b 5:keys 6:values 7:Wres 8:bres 9:Wmem 10:bmem
// ---------------------------------------------------------------------------
extern "C" void kernel_launch(void* const* d_in, const int* in_sizes, int n_in,
                              void* d_out, int out_size)
{
    const float* x      = (const float*)d_in[0];
    const float* Wq     = (const float*)d_in[1];
    const float* bq     = (const float*)d_in[2];
    const float* ln_g   = (const float*)d_in[3];
    const float* ln_b   = (const float*)d_in[4];
    const float* keys   = (const float*)d_in[5];
    const float* values = (const float*)d_in[6];
    const float* Wres   = (const float*)d_in[7];
    const float* bres   = (const float*)d_in[8];
    const float* Wmem   = (const float*)d_in[9];
    const float* bmem   = (const float*)d_in[10];
    float* out = (float*)d_out;

    cudaFuncSetAttribute(wm_gemm<false>, cudaFuncAttributeMaxDynamicSharedMemorySize, GEMM_SMEM);
    cudaFuncSetAttribute(wm_gemm<true>,  cudaFuncAttributeMaxDynamicSharedMemorySize, GEMM_SMEM);
    cudaFuncSetAttribute(attn_kernel,    cudaFuncAttributeMaxDynamicSharedMemorySize, ATTN_SMEM);

    __nv_bfloat16 *xhi, *xlo, *wqthi, *wqtlo, *qhi, *qlo;
    __nv_bfloat16 *wresthi, *wrestlo, *wmemthi, *wmemtlo, *atthi, *attlo;
    float *qraw, *att;
    cudaGetSymbolAddress((void**)&xhi,     g_xhi);      cudaGetSymbolAddress((void**)&xlo,     g_xlo);
    cudaGetSymbolAddress((void**)&wqthi,   g_wqt_hi);   cudaGetSymbolAddress((void**)&wqtlo,   g_wqt_lo);
    cudaGetSymbolAddress((void**)&qhi,     g_qhi);      cudaGetSymbolAddress((void**)&qlo,     g_qlo);
    cudaGetSymbolAddress((void**)&wresthi, g_wrest_hi); cudaGetSymbolAddress((void**)&wrestlo, g_wrest_lo);
    cudaGetSymbolAddress((void**)&wmemthi, g_wmemt_hi); cudaGetSymbolAddress((void**)&wmemtlo, g_wmemt_lo);
    cudaGetSymbolAddress((void**)&atthi,   g_atthi);    cudaGetSymbolAddress((void**)&attlo,   g_attlo);
    cudaGetSymbolAddress((void**)&qraw,    g_qraw);     cudaGetSymbolAddress((void**)&att,     g_att);

    // Prep
    split_kernel <<<(BS_TOK * 512 + 255) / 256, 256>>>(x, xhi, xlo, BS_TOK * 512);
    tsplit_kernel<<<(512 * 1024 + 255) / 256, 256>>>(Wq,   wqthi,   wqtlo,   512, 1024);
    tsplit_kernel<<<(KDn * VDn + 255) / 256, 256>>>(Wres,  wresthi, wrestlo, KDn, VDn);
    tsplit_kernel<<<(VDn * MEMn + 255) / 256, 256>>>(Wmem, wmemthi, wmemtlo, VDn, MEMn);

    // 1) q = x @ Wq + bq  (2048 x 1024, K=512)
    wm_gemm<false><<<dim3(8, 16), 256, GEMM_SMEM>>>(xhi, xlo, wqthi, wqtlo, bq, qraw,
                                                    BS_TOK, NQn * KDn, 512);
    // 2) LN -> q hi/lo ; 3) normalized keys -> hi/lo
    ln_split_kernel<<<4096, 256>>>(ln_g, ln_b);
    knorm_split_kernel<<<2048, 256>>>(keys);
    // 4) residual: g_att = q @ Wres + bres  (32768 x 128, K=64)
    wm_gemm<false><<<dim3(1, 256), 256, GEMM_SMEM>>>(qhi, qlo, wresthi, wrestlo, bres, att,
                                                     BS_TOK * NQn, VDn, KDn);
    // 5) fused attention -> att hi/lo split
    attn_kernel<<<dim3(16, 16), 256, ATTN_SMEM>>>(values);
    // 6) out = att @ Wmem + bmem (REMAP)  (32768 x 512, K=128)
    wm_gemm<true><<<dim3(4, 256), 256, GEMM_SMEM>>>(atthi, attlo, wmemthi, wmemtlo, bmem, out,
                                                    BS_TOK * NQn, MEMn, VDn);
}